// round 16
// baseline (speedup 1.0000x reference)
#include <cuda_runtime.h>
#include <cuda_fp16.h>
#include <math.h>

#define NUM_USERS 100000
#define NUM_ITEMS 50000
#define N_NODES   150000
#define DIM       64
#define XDIM      16
#define NNZ       6400000
#define BATCH     8192

#define SCAN_BLOCK 1024
#define SCAN_NBLK  ((N_NODES + SCAN_BLOCK - 1) / SCAN_BLOCK)   // 147

// Scratch
__device__ __half2 g_h0[N_NODES * (DIM / 2)];   // fp16 copy of all_emb
__device__ __half2 g_h1[N_NODES * (DIM / 2)];   // fp16 Y1
__device__ __half2 g_h2[N_NODES * (DIM / 2)];   // fp16 Y2
__device__ int     g_hist[N_NODES];
__device__ int     g_rowptr[N_NODES + 1];
__device__ int     g_cursor[N_NODES];
__device__ int     g_blocksums[SCAN_NBLK];
__device__ __align__(16) int2 g_pairs[NNZ];     // (col, val-bits) sorted by row
__device__ float   g_uacc[BATCH * DIM];
__device__ float   g_iacc[BATCH * DIM];

// ---------------------------------------------------------------------------
// Fused: convert concat(emb_user, emb_item) -> fp16 H0, and zero the histogram.
__global__ void init_kernel(const float2* __restrict__ eu,
                            const float2* __restrict__ ei,
                            __half2* __restrict__ H0,
                            int* __restrict__ hist) {
    int i = blockIdx.x * blockDim.x + threadIdx.x;
    const int nu = NUM_USERS * (DIM / 2);
    const int nt = N_NODES * (DIM / 2);
    if (i < nt) {
        float2 v = (i < nu) ? __ldg(eu + i) : __ldg(ei + (i - nu));
        H0[i] = __floats2half2_rn(v.x, v.y);
    }
    if (i < N_NODES) hist[i] = 0;
}

// 4 edges per thread via int4.
__global__ void hist_kernel(const int4* __restrict__ rows4, int* __restrict__ h) {
    int e4 = blockIdx.x * blockDim.x + threadIdx.x;
    if (e4 >= NNZ / 4) return;
    int4 r = __ldg(rows4 + e4);
    atomicAdd(&h[r.x], 1);
    atomicAdd(&h[r.y], 1);
    atomicAdd(&h[r.z], 1);
    atomicAdd(&h[r.w], 1);
}

// Inclusive scan per 1024-block, emit block sums.
__global__ void scan1_kernel(const int* __restrict__ h,
                             int* __restrict__ partial,
                             int* __restrict__ bsums) {
    __shared__ int sh[SCAN_BLOCK];
    int gid = blockIdx.x * SCAN_BLOCK + threadIdx.x;
    int v = (gid < N_NODES) ? h[gid] : 0;
    sh[threadIdx.x] = v;
    __syncthreads();
#pragma unroll
    for (int off = 1; off < SCAN_BLOCK; off <<= 1) {
        int t = (threadIdx.x >= off) ? sh[threadIdx.x - off] : 0;
        __syncthreads();
        sh[threadIdx.x] += t;
        __syncthreads();
    }
    if (gid < N_NODES) partial[gid] = sh[threadIdx.x];
    if (threadIdx.x == SCAN_BLOCK - 1) bsums[blockIdx.x] = sh[threadIdx.x];
}

// Fused scan2+scan3: each block computes its exclusive block-sum offset itself.
__global__ void scan23_kernel(const int* __restrict__ partial,
                              const int* __restrict__ bsums,
                              const int* __restrict__ h,
                              int* __restrict__ rowptr,
                              int* __restrict__ cursor) {
    __shared__ int off_s;
    if (threadIdx.x < 32) {
        int s = 0;
        for (int j = threadIdx.x; j < blockIdx.x; j += 32) s += __ldg(bsums + j);
#pragma unroll
        for (int o = 16; o; o >>= 1) s += __shfl_xor_sync(~0u, s, o);
        if (threadIdx.x == 0) off_s = s;
    }
    __syncthreads();
    int gid = blockIdx.x * SCAN_BLOCK + threadIdx.x;
    if (gid < N_NODES) {
        int incl = partial[gid] + off_s;
        rowptr[gid + 1] = incl;
        cursor[gid]     = incl - h[gid];
    }
    if (gid == 0) rowptr[0] = 0;
}

// 2 edges per thread via int2/float2 reads (R7 form).
__global__ void scatter_kernel(const int2*   __restrict__ rows2,
                               const int2*   __restrict__ cols2,
                               const float2* __restrict__ vals2,
                               int*  __restrict__ cursor,
                               int2* __restrict__ pairs) {
    int e2 = blockIdx.x * blockDim.x + threadIdx.x;
    if (e2 >= NNZ / 2) return;
    int2   r = __ldg(rows2 + e2);
    int2   c = __ldg(cols2 + e2);
    float2 v = __ldg(vals2 + e2);
    int p0 = atomicAdd(&cursor[r.x], 1);
    pairs[p0] = make_int2(c.x, __float_as_int(v.x));
    int p1 = atomicAdd(&cursor[r.y], 1);
    pairs[p1] = make_int2(c.y, __float_as_int(v.y));
}

// ---------------------------------------------------------------------------
// Warp-per-row CSR SpMM (frozen R7 structure), output fp16 only.
__global__ void spmm_h_kernel(const int*     __restrict__ rowptr,
                              const int2*    __restrict__ pairs,
                              const __half2* __restrict__ Hin,
                              __half2*       __restrict__ Hout) {
    int t = blockIdx.x * blockDim.x + threadIdx.x;
    int row = t >> 5, lane = t & 31;
    if (row >= N_NODES) return;
    int i   = __ldg(rowptr + row);
    int end = __ldg(rowptr + row + 1);
    float2 a0 = make_float2(0.f, 0.f);
    float2 a1 = make_float2(0.f, 0.f);
    float2 a2 = make_float2(0.f, 0.f);
    float2 a3 = make_float2(0.f, 0.f);
    for (; i + 3 < end; i += 4) {
        int2 p0 = __ldg(pairs + i);
        int2 p1 = __ldg(pairs + i + 1);
        int2 p2 = __ldg(pairs + i + 2);
        int2 p3 = __ldg(pairs + i + 3);
        float2 x0 = __half22float2(__ldg(Hin + (size_t)p0.x * (DIM / 2) + lane));
        float2 x1 = __half22float2(__ldg(Hin + (size_t)p1.x * (DIM / 2) + lane));
        float2 x2 = __half22float2(__ldg(Hin + (size_t)p2.x * (DIM / 2) + lane));
        float2 x3 = __half22float2(__ldg(Hin + (size_t)p3.x * (DIM / 2) + lane));
        float v0 = __int_as_float(p0.y), v1 = __int_as_float(p1.y);
        float v2 = __int_as_float(p2.y), v3 = __int_as_float(p3.y);
        a0.x += v0 * x0.x; a0.y += v0 * x0.y;
        a1.x += v1 * x1.x; a1.y += v1 * x1.y;
        a2.x += v2 * x2.x; a2.y += v2 * x2.y;
        a3.x += v3 * x3.x; a3.y += v3 * x3.y;
    }
    for (; i < end; ++i) {
        int2 p0 = __ldg(pairs + i);
        float2 x0 = __half22float2(__ldg(Hin + (size_t)p0.x * (DIM / 2) + lane));
        float v0 = __int_as_float(p0.y);
        a0.x += v0 * x0.x; a0.y += v0 * x0.y;
    }
    float2 s = make_float2(a0.x + a1.x + a2.x + a3.x,
                           a0.y + a1.y + a2.y + a3.y);
    Hout[(size_t)row * (DIM / 2) + lane] = __floats2half2_rn(s.x, s.y);
}

// Warp per (batch element, side): acc = x0 + h1 + h2 + (A @ h2)[row].
// Direct terms read from the fp16 copies (no separate fp32 buffers).
__global__ void gather3_kernel(const float* __restrict__ emb_user,
                               const float* __restrict__ emb_item,
                               const __half2* __restrict__ H1,
                               const __half2* __restrict__ H2,
                               const int*   __restrict__ rowptr,
                               const int2*  __restrict__ pairs,
                               const int*   __restrict__ users,
                               const int*   __restrict__ items,
                               float* __restrict__ uacc,
                               float* __restrict__ iacc) {
    int t = blockIdx.x * blockDim.x + threadIdx.x;
    int w = t >> 5, lane = t & 31;
    if (w >= 2 * BATCH) return;
    bool isU = (w < BATCH);
    int b = isU ? w : (w - BATCH);
    int r, node;
    const float2* x0;
    if (isU) {
        r = __ldg(users + b); node = r;
        x0 = (const float2*)(emb_user + (size_t)r * DIM);
    } else {
        r = __ldg(items + b); node = NUM_USERS + r;
        x0 = (const float2*)(emb_item + (size_t)r * DIM);
    }
    float2 a  = __ldg(x0 + lane);
    float2 y1 = __half22float2(__ldg(H1 + (size_t)node * (DIM / 2) + lane));
    float2 y2 = __half22float2(__ldg(H2 + (size_t)node * (DIM / 2) + lane));
    float2 acc = make_float2(a.x + y1.x + y2.x, a.y + y1.y + y2.y);
    int i   = __ldg(rowptr + node);
    int end = __ldg(rowptr + node + 1);
    for (; i + 1 < end; i += 2) {
        int2 p0 = __ldg(pairs + i);
        int2 p1 = __ldg(pairs + i + 1);
        float2 x0f = __half22float2(__ldg(H2 + (size_t)p0.x * (DIM / 2) + lane));
        float2 x1f = __half22float2(__ldg(H2 + (size_t)p1.x * (DIM / 2) + lane));
        float v0 = __int_as_float(p0.y), v1 = __int_as_float(p1.y);
        acc.x += v0 * x0f.x + v1 * x1f.x;
        acc.y += v0 * x0f.y + v1 * x1f.y;
    }
    if (i < end) {
        int2 p0 = __ldg(pairs + i);
        float2 x0f = __half22float2(__ldg(H2 + (size_t)p0.x * (DIM / 2) + lane));
        float v0 = __int_as_float(p0.y);
        acc.x += v0 * x0f.x;
        acc.y += v0 * x0f.y;
    }
    float* dst = (isU ? uacc : iacc) + (size_t)b * DIM;
    ((float2*)dst)[lane] = acc;
}

// Warp per batch element: softmax(users_mix) . sigmoid(items_mix) over 80 dims.
__global__ void final_kernel(const float* __restrict__ uacc,
                             const float* __restrict__ iacc,
                             const float* __restrict__ exu,
                             const float* __restrict__ exi1,
                             const float* __restrict__ exi0,
                             const float* __restrict__ wu_p,
                             const float* __restrict__ wi_p,
                             const int*   __restrict__ users,
                             const int*   __restrict__ items,
                             const int*   __restrict__ xij,
                             float* __restrict__ out) {
    int t = blockIdx.x * blockDim.x + threadIdx.x;
    int b = t >> 5, lane = t & 31;
    if (b >= BATCH) return;
    int u  = __ldg(users + b);
    int it = __ldg(items + b);
    const float* xi = __ldg(xij + b) ? exi1 : exi0;
    float wu = __ldg(wu_p) * 0.25f;   // light_out = acc / (N_LAYERS+1)
    float wi = __ldg(wi_p) * 0.25f;

    float uv[3], iv[3];
#pragma unroll
    for (int k = 0; k < 3; k++) {
        int d = lane + 32 * k;
        if (d < DIM) {
            uv[k] = wu * uacc[(size_t)b * DIM + d];
            iv[k] = wi * iacc[(size_t)b * DIM + d];
        } else if (d < DIM + XDIM) {
            uv[k] = exu[(size_t)u * XDIM + (d - DIM)];
            iv[k] = xi [(size_t)it * XDIM + (d - DIM)];
        } else {
            uv[k] = -1e30f;
            iv[k] = 0.f;
        }
    }
    float m = fmaxf(fmaxf(uv[0], uv[1]), uv[2]);
#pragma unroll
    for (int o = 16; o; o >>= 1) m = fmaxf(m, __shfl_xor_sync(~0u, m, o));
    float e[3]; float s = 0.f;
#pragma unroll
    for (int k = 0; k < 3; k++) { e[k] = expf(uv[k] - m); s += e[k]; }
#pragma unroll
    for (int o = 16; o; o >>= 1) s += __shfl_xor_sync(~0u, s, o);
    float inv = 1.f / s;
    float g = 0.f;
#pragma unroll
    for (int k = 0; k < 3; k++) {
        float sg = 1.f / (1.f + expf(-iv[k]));
        g += e[k] * inv * sg;
    }
#pragma unroll
    for (int o = 16; o; o >>= 1) g += __shfl_xor_sync(~0u, g, o);
    if (lane == 0) out[b] = g;
}

// ---------------------------------------------------------------------------
extern "C" void kernel_launch(void* const* d_in, const int* in_sizes, int n_in,
                              void* d_out, int out_size) {
    const float* emb_user = (const float*)d_in[0];
    const float* emb_item = (const float*)d_in[1];
    const float* exu      = (const float*)d_in[2];
    const float* exi1     = (const float*)d_in[3];
    const float* exi0     = (const float*)d_in[4];
    const float* wu       = (const float*)d_in[5];
    const float* wi       = (const float*)d_in[6];
    const float* gvals    = (const float*)d_in[7];
    const int*   grows    = (const int*)d_in[8];
    const int*   gcols    = (const int*)d_in[9];
    const int*   users    = (const int*)d_in[10];
    const int*   items    = (const int*)d_in[11];
    const int*   xij      = (const int*)d_in[12];
    float* out = (float*)d_out;

    float *ua, *ia;
    __half2 *h0, *h1, *h2;
    int *hist, *rowptr, *cursor, *bsums;
    int2 *pairs;
    cudaGetSymbolAddress((void**)&h0,     g_h0);
    cudaGetSymbolAddress((void**)&h1,     g_h1);
    cudaGetSymbolAddress((void**)&h2,     g_h2);
    cudaGetSymbolAddress((void**)&ua,     g_uacc);
    cudaGetSymbolAddress((void**)&ia,     g_iacc);
    cudaGetSymbolAddress((void**)&hist,   g_hist);
    cudaGetSymbolAddress((void**)&rowptr, g_rowptr);
    cudaGetSymbolAddress((void**)&cursor, g_cursor);
    cudaGetSymbolAddress((void**)&bsums,  g_blocksums);
    cudaGetSymbolAddress((void**)&pairs,  g_pairs);

    const int hist4Blocks  = (NNZ / 4 + 255) / 256;                // 6250
    const int scat2Blocks  = (NNZ / 2 + 255) / 256;                // 12500
    const int convBlocks   = (N_NODES * (DIM / 2) + 255) / 256;    // 18750
    const int spmmBlocks   = (N_NODES * 32 + 255) / 256;           // 18750
    const int gatherBlocks = (2 * BATCH * 32) / 256;               // 2048

    // --- CSR build (counting sort) + fp16 conversion of all_emb ---
    init_kernel<<<convBlocks, 256>>>((const float2*)emb_user,
                                     (const float2*)emb_item, h0, hist);
    hist_kernel<<<hist4Blocks, 256>>>((const int4*)grows, hist);
    scan1_kernel<<<SCAN_NBLK, SCAN_BLOCK>>>(hist, cursor /*partial*/, bsums);
    scan23_kernel<<<SCAN_NBLK, SCAN_BLOCK>>>(cursor, bsums, hist, rowptr, cursor);
    scatter_kernel<<<scat2Blocks, 256>>>((const int2*)grows, (const int2*)gcols,
                                         (const float2*)gvals, cursor, pairs);

    // --- Layers 1 and 2: full SpMM, fp16 gather / fp32 accumulate ---
    spmm_h_kernel<<<spmmBlocks, 256>>>(rowptr, pairs, h0, h1);
    spmm_h_kernel<<<spmmBlocks, 256>>>(rowptr, pairs, h1, h2);

    // --- Layer 3 only at batch rows, fused with accumulation ---
    gather3_kernel<<<gatherBlocks, 256>>>(emb_user, emb_item, h1, h2,
                                          rowptr, pairs, users, items, ua, ia);

    final_kernel<<<(BATCH * 32) / 256, 256>>>(ua, ia, exu, exi1, exi0,
                                              wu, wi, users, items, xij, out);
}

// round 17
// speedup vs baseline: 1.1267x; 1.1267x over previous
#include <cuda_runtime.h>
#include <cuda_fp16.h>
#include <math.h>

#define NUM_USERS 100000
#define NUM_ITEMS 50000
#define N_NODES   150000
#define DIM       64
#define XDIM      16
#define NNZ       6400000
#define BATCH     8192

#define SCAN_BLOCK 1024
#define SCAN_NBLK  ((N_NODES + SCAN_BLOCK - 1) / SCAN_BLOCK)   // 147

// Scratch
__device__ float   g_bufA[N_NODES * DIM];       // Y1 (fp32)
__device__ float   g_bufB[N_NODES * DIM];       // Y2 (fp32)
__device__ __half2 g_h0[N_NODES * (DIM / 2)];   // fp16 copy of all_emb
__device__ __half2 g_h1[N_NODES * (DIM / 2)];   // fp16 copy of Y1
__device__ __half2 g_h2[N_NODES * (DIM / 2)];   // fp16 copy of Y2
__device__ int     g_hist[N_NODES];
__device__ int     g_rowptr[N_NODES + 1];
__device__ int     g_cursor[N_NODES];
__device__ int     g_blocksums[SCAN_NBLK];
__device__ int2    g_pairs[NNZ];                // (col, val-bits) sorted by row
__device__ float   g_uacc[BATCH * DIM];
__device__ float   g_iacc[BATCH * DIM];

// ---------------------------------------------------------------------------
// Fused: convert concat(emb_user, emb_item) -> fp16 H0, and zero the histogram.
__global__ void init_kernel(const float2* __restrict__ eu,
                            const float2* __restrict__ ei,
                            __half2* __restrict__ H0,
                            int* __restrict__ hist) {
    int i = blockIdx.x * blockDim.x + threadIdx.x;
    const int nu = NUM_USERS * (DIM / 2);
    const int nt = N_NODES * (DIM / 2);
    if (i < nt) {
        float2 v = (i < nu) ? __ldg(eu + i) : __ldg(ei + (i - nu));
        H0[i] = __floats2half2_rn(v.x, v.y);
    }
    if (i < N_NODES) hist[i] = 0;
}

__global__ void hist_kernel(const int* __restrict__ rows, int* __restrict__ h) {
    int e = blockIdx.x * blockDim.x + threadIdx.x;
    if (e < NNZ) atomicAdd(&h[__ldg(rows + e)], 1);
}

// Inclusive scan per 1024-block, emit block sums.
__global__ void scan1_kernel(const int* __restrict__ h,
                             int* __restrict__ partial,
                             int* __restrict__ bsums) {
    __shared__ int sh[SCAN_BLOCK];
    int gid = blockIdx.x * SCAN_BLOCK + threadIdx.x;
    int v = (gid < N_NODES) ? h[gid] : 0;
    sh[threadIdx.x] = v;
    __syncthreads();
#pragma unroll
    for (int off = 1; off < SCAN_BLOCK; off <<= 1) {
        int t = (threadIdx.x >= off) ? sh[threadIdx.x - off] : 0;
        __syncthreads();
        sh[threadIdx.x] += t;
        __syncthreads();
    }
    if (gid < N_NODES) partial[gid] = sh[threadIdx.x];
    if (threadIdx.x == SCAN_BLOCK - 1) bsums[blockIdx.x] = sh[threadIdx.x];
}

// Fused scan2+scan3: each block computes its exclusive block-sum offset itself
// (147 entries, warp-strided), then writes rowptr and cursor.
__global__ void scan23_kernel(const int* __restrict__ partial,
                              const int* __restrict__ bsums,
                              const int* __restrict__ h,
                              int* __restrict__ rowptr,
                              int* __restrict__ cursor) {
    __shared__ int off_s;
    if (threadIdx.x < 32) {
        int s = 0;
        for (int j = threadIdx.x; j < blockIdx.x; j += 32) s += __ldg(bsums + j);
#pragma unroll
        for (int o = 16; o; o >>= 1) s += __shfl_xor_sync(~0u, s, o);
        if (threadIdx.x == 0) off_s = s;
    }
    __syncthreads();
    int gid = blockIdx.x * SCAN_BLOCK + threadIdx.x;
    if (gid < N_NODES) {
        int incl = partial[gid] + off_s;
        rowptr[gid + 1] = incl;
        cursor[gid]     = incl - h[gid];
    }
    if (gid == 0) rowptr[0] = 0;
}

__global__ void scatter_kernel(const int*   __restrict__ rows,
                               const int*   __restrict__ cols,
                               const float* __restrict__ vals,
                               int*  __restrict__ cursor,
                               int2* __restrict__ pairs) {
    int e = blockIdx.x * blockDim.x + threadIdx.x;
    if (e >= NNZ) return;
    int r = __ldg(rows + e);
    int p = atomicAdd(&cursor[r], 1);
    int2 pr;
    pr.x = __ldg(cols + e);
    pr.y = __float_as_int(__ldg(vals + e));
    pairs[p] = pr;
}

// Warp-per-row CSR SpMM with fp16 gather operand, fp32 accumulate.
// Writes fp32 Y and an fp16 copy Hout (input for the next pass).
__global__ void spmm_h_kernel(const int*     __restrict__ rowptr,
                              const int2*    __restrict__ pairs,
                              const __half2* __restrict__ Hin,
                              float*         __restrict__ Y,
                              __half2*       __restrict__ Hout) {
    int t = blockIdx.x * blockDim.x + threadIdx.x;
    int row = t >> 5, lane = t & 31;
    if (row >= N_NODES) return;
    int i   = __ldg(rowptr + row);
    int end = __ldg(rowptr + row + 1);
    float2 a0 = make_float2(0.f, 0.f);
    float2 a1 = make_float2(0.f, 0.f);
    float2 a2 = make_float2(0.f, 0.f);
    float2 a3 = make_float2(0.f, 0.f);
    for (; i + 3 < end; i += 4) {
        int2 p0 = __ldg(pairs + i);
        int2 p1 = __ldg(pairs + i + 1);
        int2 p2 = __ldg(pairs + i + 2);
        int2 p3 = __ldg(pairs + i + 3);
        float2 x0 = __half22float2(__ldg(Hin + (size_t)p0.x * (DIM / 2) + lane));
        float2 x1 = __half22float2(__ldg(Hin + (size_t)p1.x * (DIM / 2) + lane));
        float2 x2 = __half22float2(__ldg(Hin + (size_t)p2.x * (DIM / 2) + lane));
        float2 x3 = __half22float2(__ldg(Hin + (size_t)p3.x * (DIM / 2) + lane));
        float v0 = __int_as_float(p0.y), v1 = __int_as_float(p1.y);
        float v2 = __int_as_float(p2.y), v3 = __int_as_float(p3.y);
        a0.x += v0 * x0.x; a0.y += v0 * x0.y;
        a1.x += v1 * x1.x; a1.y += v1 * x1.y;
        a2.x += v2 * x2.x; a2.y += v2 * x2.y;
        a3.x += v3 * x3.x; a3.y += v3 * x3.y;
    }
    for (; i < end; ++i) {
        int2 p0 = __ldg(pairs + i);
        float2 x0 = __half22float2(__ldg(Hin + (size_t)p0.x * (DIM / 2) + lane));
        float v0 = __int_as_float(p0.y);
        a0.x += v0 * x0.x; a0.y += v0 * x0.y;
    }
    float2 s = make_float2(a0.x + a1.x + a2.x + a3.x,
                           a0.y + a1.y + a2.y + a3.y);
    ((float2*)(Y + (size_t)row * DIM))[lane] = s;
    Hout[(size_t)row * (DIM / 2) + lane] = __floats2half2_rn(s.x, s.y);
}

// Warp per (batch element, side): acc = x0 + y1 + y2 + (A @ y2)[row], with the
// direct terms in fp32 and the layer-3 neighbor gather from the fp16 copy.
__global__ void gather3_kernel(const float* __restrict__ emb_user,
                               const float* __restrict__ emb_item,
                               const float* __restrict__ Y1,
                               const float* __restrict__ Y2,
                               const __half2* __restrict__ H2,
                               const int*   __restrict__ rowptr,
                               const int2*  __restrict__ pairs,
                               const int*   __restrict__ users,
                               const int*   __restrict__ items,
                               float* __restrict__ uacc,
                               float* __restrict__ iacc) {
    int t = blockIdx.x * blockDim.x + threadIdx.x;
    int w = t >> 5, lane = t & 31;
    if (w >= 2 * BATCH) return;
    bool isU = (w < BATCH);
    int b = isU ? w : (w - BATCH);
    int r, node;
    const float2* x0;
    if (isU) {
        r = __ldg(users + b); node = r;
        x0 = (const float2*)(emb_user + (size_t)r * DIM);
    } else {
        r = __ldg(items + b); node = NUM_USERS + r;
        x0 = (const float2*)(emb_item + (size_t)r * DIM);
    }
    float2 a  = __ldg(x0 + lane);
    float2 y1 = ((const float2*)(Y1 + (size_t)node * DIM))[lane];
    float2 y2 = ((const float2*)(Y2 + (size_t)node * DIM))[lane];
    float2 acc = make_float2(a.x + y1.x + y2.x, a.y + y1.y + y2.y);
    int i   = __ldg(rowptr + node);
    int end = __ldg(rowptr + node + 1);
    for (; i + 1 < end; i += 2) {
        int2 p0 = __ldg(pairs + i);
        int2 p1 = __ldg(pairs + i + 1);
        float2 x0f = __half22float2(__ldg(H2 + (size_t)p0.x * (DIM / 2) + lane));
        float2 x1f = __half22float2(__ldg(H2 + (size_t)p1.x * (DIM / 2) + lane));
        float v0 = __int_as_float(p0.y), v1 = __int_as_float(p1.y);
        acc.x += v0 * x0f.x + v1 * x1f.x;
        acc.y += v0 * x0f.y + v1 * x1f.y;
    }
    if (i < end) {
        int2 p0 = __ldg(pairs + i);
        float2 x0f = __half22float2(__ldg(H2 + (size_t)p0.x * (DIM / 2) + lane));
        float v0 = __int_as_float(p0.y);
        acc.x += v0 * x0f.x;
        acc.y += v0 * x0f.y;
    }
    float* dst = (isU ? uacc : iacc) + (size_t)b * DIM;
    ((float2*)dst)[lane] = acc;
}

// Warp per batch element: softmax(users_mix) . sigmoid(items_mix) over 80 dims.
__global__ void final_kernel(const float* __restrict__ uacc,
                             const float* __restrict__ iacc,
                             const float* __restrict__ exu,
                             const float* __restrict__ exi1,
                             const float* __restrict__ exi0,
                             const float* __restrict__ wu_p,
                             const float* __restrict__ wi_p,
                             const int*   __restrict__ users,
                             const int*   __restrict__ items,
                             const int*   __restrict__ xij,
                             float* __restrict__ out) {
    int t = blockIdx.x * blockDim.x + threadIdx.x;
    int b = t >> 5, lane = t & 31;
    if (b >= BATCH) return;
    int u  = __ldg(users + b);
    int it = __ldg(items + b);
    const float* xi = __ldg(xij + b) ? exi1 : exi0;
    float wu = __ldg(wu_p) * 0.25f;   // light_out = acc / (N_LAYERS+1)
    float wi = __ldg(wi_p) * 0.25f;

    float uv[3], iv[3];
#pragma unroll
    for (int k = 0; k < 3; k++) {
        int d = lane + 32 * k;
        if (d < DIM) {
            uv[k] = wu * uacc[(size_t)b * DIM + d];
            iv[k] = wi * iacc[(size_t)b * DIM + d];
        } else if (d < DIM + XDIM) {
            uv[k] = exu[(size_t)u * XDIM + (d - DIM)];
            iv[k] = xi [(size_t)it * XDIM + (d - DIM)];
        } else {
            uv[k] = -1e30f;
            iv[k] = 0.f;
        }
    }
    float m = fmaxf(fmaxf(uv[0], uv[1]), uv[2]);
#pragma unroll
    for (int o = 16; o; o >>= 1) m = fmaxf(m, __shfl_xor_sync(~0u, m, o));
    float e[3]; float s = 0.f;
#pragma unroll
    for (int k = 0; k < 3; k++) { e[k] = expf(uv[k] - m); s += e[k]; }
#pragma unroll
    for (int o = 16; o; o >>= 1) s += __shfl_xor_sync(~0u, s, o);
    float inv = 1.f / s;
    float g = 0.f;
#pragma unroll
    for (int k = 0; k < 3; k++) {
        float sg = 1.f / (1.f + expf(-iv[k]));
        g += e[k] * inv * sg;
    }
#pragma unroll
    for (int o = 16; o; o >>= 1) g += __shfl_xor_sync(~0u, g, o);
    if (lane == 0) out[b] = g;
}

// ---------------------------------------------------------------------------
extern "C" void kernel_launch(void* const* d_in, const int* in_sizes, int n_in,
                              void* d_out, int out_size) {
    const float* emb_user = (const float*)d_in[0];
    const float* emb_item = (const float*)d_in[1];
    const float* exu      = (const float*)d_in[2];
    const float* exi1     = (const float*)d_in[3];
    const float* exi0     = (const float*)d_in[4];
    const float* wu       = (const float*)d_in[5];
    const float* wi       = (const float*)d_in[6];
    const float* gvals    = (const float*)d_in[7];
    const int*   grows    = (const int*)d_in[8];
    const int*   gcols    = (const int*)d_in[9];
    const int*   users    = (const int*)d_in[10];
    const int*   items    = (const int*)d_in[11];
    const int*   xij      = (const int*)d_in[12];
    float* out = (float*)d_out;

    float *A, *B, *ua, *ia;
    __half2 *h0, *h1, *h2;
    int *hist, *rowptr, *cursor, *bsums;
    int2 *pairs;
    cudaGetSymbolAddress((void**)&A,      g_bufA);
    cudaGetSymbolAddress((void**)&B,      g_bufB);
    cudaGetSymbolAddress((void**)&h0,     g_h0);
    cudaGetSymbolAddress((void**)&h1,     g_h1);
    cudaGetSymbolAddress((void**)&h2,     g_h2);
    cudaGetSymbolAddress((void**)&ua,     g_uacc);
    cudaGetSymbolAddress((void**)&ia,     g_iacc);
    cudaGetSymbolAddress((void**)&hist,   g_hist);
    cudaGetSymbolAddress((void**)&rowptr, g_rowptr);
    cudaGetSymbolAddress((void**)&cursor, g_cursor);
    cudaGetSymbolAddress((void**)&bsums,  g_blocksums);
    cudaGetSymbolAddress((void**)&pairs,  g_pairs);

    const int edgeBlocks   = (NNZ + 255) / 256;                    // 25000
    const int convBlocks   = (N_NODES * (DIM / 2) + 255) / 256;    // 18750
    const int spmmBlocks   = (N_NODES * 32 + 255) / 256;           // 18750
    const int gatherBlocks = (2 * BATCH * 32) / 256;               // 2048

    // --- CSR build (counting sort) + fp16 conversion of all_emb ---
    init_kernel<<<convBlocks, 256>>>((const float2*)emb_user,
                                     (const float2*)emb_item, h0, hist);
    hist_kernel<<<edgeBlocks, 256>>>(grows, hist);
    scan1_kernel<<<SCAN_NBLK, SCAN_BLOCK>>>(hist, cursor /*partial*/, bsums);
    scan23_kernel<<<SCAN_NBLK, SCAN_BLOCK>>>(cursor, bsums, hist, rowptr, cursor);
    scatter_kernel<<<edgeBlocks, 256>>>(grows, gcols, gvals, cursor, pairs);

    // --- Layers 1 and 2: full SpMM, fp16 gather / fp32 accumulate ---
    spmm_h_kernel<<<spmmBlocks, 256>>>(rowptr, pairs, h0, A, h1);
    spmm_h_kernel<<<spmmBlocks, 256>>>(rowptr, pairs, h1, B, h2);

    // --- Layer 3 only at batch rows, fused with accumulation ---
    gather3_kernel<<<gatherBlocks, 256>>>(emb_user, emb_item, A, B, h2,
                                          rowptr, pairs, users, items, ua, ia);

    final_kernel<<<(BATCH * 32) / 256, 256>>>(ua, ia, exu, exi1, exi0,
                                              wu, wi, users, items, xij, out);
}